// round 15
// baseline (speedup 1.0000x reference)
#include <cuda_runtime.h>
#include <cuda_fp16.h>
#include <cstdint>
#include <math.h>

#define DM   512
#define DFF  2048
#define NH   8
#define DH   64
#define BB   2
#define SEQ  2048
#define ROWS (BB*SEQ)   // 4096
#define QKV_LD 1536

// Q projection pre-scale: (1/sqrt(64)) * log2(e), so softmax uses ex2 directly
#define QSCALE 0.18033688011112042f

// ---------------- static scratch (no allocations allowed) ----------------
__device__ __half  g_Qs  [ROWS*DM];           // Q, pre-scaled
__device__ __half  g_Kn  [ROWS*DM];           // K, natural layout
__device__ __half  g_Vt  [BB*NH*DH*SEQ];      // V transposed [b,h,dim][key]
__device__ __half  g_O   [ROWS*DM];
__device__ float   g_T   [ROWS*DM];           // fp32 (LN input)
__device__ __half  g_Z   [ROWS*DM];
__device__ __half  g_H1  [ROWS*DFF];
__device__ __half  g_WqkvT[QKV_LD*DM];        // [n][k]; Wq part pre-scaled
__device__ __half  g_WoT [DM*DM];
__device__ __half  g_W1T [DFF*DM];
__device__ __half  g_W2T [DM*DFF];
__device__ float   g_bqkv[QKV_LD];

__device__ __forceinline__ uint32_t pack_f16x2(float lo, float hi) {
    uint32_t r;
    asm("cvt.rn.f16x2.f32 %0, %1, %2;" : "=r"(r) : "f"(hi), "f"(lo));
    return r;
}
__device__ __forceinline__ uint32_t h2ex2(uint32_t x) {
    uint32_t r;
    asm("ex2.approx.f16x2 %0, %1;" : "=r"(r) : "r"(x));
    return r;
}
__device__ __forceinline__ uint32_t smem_u32(const void* p) {
    uint32_t a;
    asm("{ .reg .u64 t; cvta.to.shared.u64 t, %1; cvt.u32.u64 %0, t; }" : "=r"(a) : "l"(p));
    return a;
}

#define MMA_F16(d0,d1,d2,d3, a0,a1,a2,a3, b0,b1) \
    asm volatile("mma.sync.aligned.m16n8k16.row.col.f32.f16.f16.f32 " \
        "{%0,%1,%2,%3}, {%4,%5,%6,%7}, {%8,%9}, {%0,%1,%2,%3};" \
        : "+f"(d0), "+f"(d1), "+f"(d2), "+f"(d3) \
        : "r"(a0), "r"(a1), "r"(a2), "r"(a3), "r"(b0), "r"(b1))

#define LDSM_X4(r0,r1,r2,r3, addr) \
    asm volatile("ldmatrix.sync.aligned.m8n8.x4.shared.b16 {%0,%1,%2,%3}, [%4];" \
        : "=r"(r0), "=r"(r1), "=r"(r2), "=r"(r3) : "r"(addr))

#define CP_ASYNC16(saddr, gptr) \
    asm volatile("cp.async.cg.shared.global [%0], [%1], 16;" :: "r"(saddr), "l"(gptr))
#define CP_COMMIT() asm volatile("cp.async.commit_group;" ::: "memory")
#define CP_WAIT_N(n) asm volatile("cp.async.wait_group %0;" :: "n"(n) : "memory")
#define CP_WAIT0()  asm volatile("cp.async.wait_group 0;" ::: "memory")

// =====================================================================
// prep_weights: transposes + fp16 conversion + bias concat (+Q scale fold)
// =====================================================================
__global__ void prep_weights(
    const float* __restrict__ Wq, const float* __restrict__ Wk,
    const float* __restrict__ Wv, const float* __restrict__ Wo,
    const float* __restrict__ W1, const float* __restrict__ W2,
    const float* __restrict__ bq, const float* __restrict__ bk,
    const float* __restrict__ bv,
    __half* __restrict__ QKVT, __half* __restrict__ WoT,
    __half* __restrict__ W1T,  __half* __restrict__ W2T,
    float* __restrict__ bqkv)
{
    int idx = blockIdx.x * 256 + threadIdx.x;
    switch (blockIdx.y) {
    case 0: {
        if (idx >= QKV_LD * DM) return;
        int n = idx >> 9, k = idx & 511;
        const float* W = (n < 512) ? Wq : ((n < 1024) ? Wk : Wv);
        float sc = (n < 512) ? QSCALE : 1.0f;
        int nl = n & 511;
        QKVT[idx] = __float2half(sc * W[((size_t)(nl >> 6) * 512 + k) * 64 + (nl & 63)]);
    } break;
    case 1: {
        if (idx >= DM * DM) return;
        int n = idx >> 9, k = idx & 511;
        WoT[idx] = __float2half(Wo[(size_t)k * DM + n]);
    } break;
    case 2: {
        if (idx >= DFF * DM) return;
        int n = idx >> 9, k = idx & 511;
        W1T[idx] = __float2half(W1[(size_t)k * DFF + n]);
    } break;
    case 3: {
        if (idx >= DM * DFF) return;
        int n = idx >> 11, k = idx & 2047;
        W2T[idx] = __float2half(W2[(size_t)k * DM + n]);
    } break;
    case 4: {
        if (idx >= 512) return;
        bqkv[idx]        = bq[idx] * QSCALE;
        bqkv[512 + idx]  = bk[idx];
        bqkv[1024 + idx] = bv[idx];
    } break;
    }
}

__global__ void round_z(const float* __restrict__ z, __half* __restrict__ out) {
    int i = blockIdx.x * 256 + threadIdx.x;
    out[i] = __float2half(z[i]);
}

// =====================================================================
// FP16 mma.sync GEMM (m16n8k16), cp.async STAGES-deep, ldmatrix frags.
// CTA 128x128, K-slab 64 (128B rows, chunk-XOR swizzle).
// STAGES=3 -> 2 CTA/SM (big grids); STAGES=5 -> 1 CTA/SM with deep
// prefetch (short-K, grid<=#SM shapes: Wo, W2).
// =====================================================================
#define G_SMEM(STAGES) ((STAGES) * 32768)

template<int STAGES, bool RELU, bool RES, bool F32OUT, bool QKVO>
__global__ void __launch_bounds__(256, (STAGES == 3 ? 2 : 1)) mma_gemm(
    const __half* __restrict__ A, const __half* __restrict__ BT,
    const float* __restrict__ bias, const __half* __restrict__ R,
    float* __restrict__ Cf, __half* __restrict__ Ch,
    __half* __restrict__ CK, __half* __restrict__ CV,
    int M, int N, int K)
{
    extern __shared__ char smc[];
    const uint32_t sbase = smem_u32(smc);

    const int tid = threadIdx.x;
    const int wid = tid >> 5, l = tid & 31;
    const int lr  = l >> 2, la = l & 3;
    const int wm  = wid & 1;
    const int wn  = wid >> 1;
    const int m0  = blockIdx.y * 128;
    const int n0  = blockIdx.x * 128;
    const int NS  = K >> 6;

    const uint32_t ar7   = (uint32_t)(l & 7);
    const uint32_t achi  = (uint32_t)(l >> 4);
    const uint32_t bchi  = (uint32_t)((l >> 3) & 1);
    const uint32_t bjh   = (uint32_t)((l >> 4) & 1);
    uint32_t arel[4];
#pragma unroll
    for (int i = 0; i < 4; i++)
        arel[i] = (uint32_t)((wm * 64 + i * 16 + (l & 15)) * 128);
    uint32_t brel[2];
#pragma unroll
    for (int p = 0; p < 2; p++)
        brel[p] = (uint32_t)((wn * 32 + (p * 2 + bjh) * 8 + (l & 7)) * 128);

    const int srow = tid >> 1;
    const int cb   = (tid & 1) * 4;
    uint32_t soff[4];
#pragma unroll
    for (int i = 0; i < 4; i++)
        soff[i] = (uint32_t)(srow * 128) + (uint32_t)(((cb + i) ^ (srow & 7)) * 16);

    const __half* Ag = A  + (size_t)m0 * K;
    const __half* Bg = BT + (size_t)n0 * K;

    // prologue: issue STAGES-1 slabs
#pragma unroll
    for (int s = 0; s < STAGES - 1; s++) {
        uint32_t st = sbase + (uint32_t)s * 32768u;
        const __half* Ap = Ag + (size_t)srow * K + s * 64 + cb * 8;
        const __half* Bp = Bg + (size_t)srow * K + s * 64 + cb * 8;
#pragma unroll
        for (int i = 0; i < 4; i++) {
            CP_ASYNC16(st + soff[i],           Ap + i * 8);
            CP_ASYNC16(st + 16384u + soff[i],  Bp + i * 8);
        }
        CP_COMMIT();
    }

    float acc[4][4][4] = {};

    for (int s = 0; s < NS; s++) {
        CP_WAIT_N(STAGES - 2);
        __syncthreads();

        if (s + STAGES - 1 < NS) {
            int sn = s + STAGES - 1;
            uint32_t st = sbase + (uint32_t)(sn % STAGES) * 32768u;
            const __half* Ap = Ag + (size_t)srow * K + sn * 64 + cb * 8;
            const __half* Bp = Bg + (size_t)srow * K + sn * 64 + cb * 8;
#pragma unroll
            for (int i = 0; i < 4; i++) {
                CP_ASYNC16(st + soff[i],          Ap + i * 8);
                CP_ASYNC16(st + 16384u + soff[i], Bp + i * 8);
            }
            CP_COMMIT();
        }

        const uint32_t stA = sbase + (uint32_t)(s % STAGES) * 32768u;
        const uint32_t stB = stA + 16384u;

#pragma unroll
        for (int kc = 0; kc < 4; kc++) {
            const uint32_t axo = ((2u * kc + achi) ^ ar7) * 16u;
            const uint32_t bxo = ((2u * kc + bchi) ^ ar7) * 16u;
            uint32_t a[4][4], b[4][2];
#pragma unroll
            for (int i = 0; i < 4; i++)
                LDSM_X4(a[i][0], a[i][1], a[i][2], a[i][3], stA + arel[i] + axo);
            LDSM_X4(b[0][0], b[0][1], b[1][0], b[1][1], stB + brel[0] + bxo);
            LDSM_X4(b[2][0], b[2][1], b[3][0], b[3][1], stB + brel[1] + bxo);
#pragma unroll
            for (int i = 0; i < 4; i++)
#pragma unroll
                for (int j = 0; j < 4; j++)
                    MMA_F16(acc[i][j][0], acc[i][j][1], acc[i][j][2], acc[i][j][3],
                            a[i][0], a[i][1], a[i][2], a[i][3], b[j][0], b[j][1]);
        }
    }

    // ---- epilogue ----
#pragma unroll
    for (int i = 0; i < 4; i++) {
        int mlo = m0 + wm * 64 + i * 16 + lr;
#pragma unroll
        for (int j = 0; j < 4; j++) {
            int n = n0 + wn * 32 + j * 8 + la * 2;
            float2 bz = *(const float2*)(bias + n);
            float2 v0 = make_float2(acc[i][j][0] + bz.x, acc[i][j][1] + bz.y);
            float2 v1 = make_float2(acc[i][j][2] + bz.x, acc[i][j][3] + bz.y);
            if (QKVO) {
                int part = n >> 9, nl = n & 511;
                if (part == 0) {
                    *(uint32_t*)(Ch + (size_t)mlo * DM + nl) = pack_f16x2(v0.x, v0.y);
                    *(uint32_t*)(Ch + (size_t)(mlo + 8) * DM + nl) = pack_f16x2(v1.x, v1.y);
                } else if (part == 1) {
                    *(uint32_t*)(CK + (size_t)mlo * DM + nl) = pack_f16x2(v0.x, v0.y);
                    *(uint32_t*)(CK + (size_t)(mlo + 8) * DM + nl) = pack_f16x2(v1.x, v1.y);
                } else {
                    int h = nl >> 6, d = nl & 63;
                    int key = mlo & (SEQ - 1);
                    int bb_ = mlo >> 11;
                    size_t vrow = ((size_t)bb_ * NH + h) * 64 + d;
                    CV[vrow * SEQ + key]           = __float2half(v0.x);
                    CV[(vrow + 1) * SEQ + key]     = __float2half(v0.y);
                    CV[vrow * SEQ + key + 8]       = __float2half(v1.x);
                    CV[(vrow + 1) * SEQ + key + 8] = __float2half(v1.y);
                }
            } else {
                if (RES) {
                    float2 r0 = __half22float2(*(const __half2*)(R + (size_t)mlo * N + n));
                    float2 r1 = __half22float2(*(const __half2*)(R + (size_t)(mlo + 8) * N + n));
                    v0.x += r0.x; v0.y += r0.y; v1.x += r1.x; v1.y += r1.y;
                }
                if (RELU) {
                    v0.x = fmaxf(v0.x, 0.f); v0.y = fmaxf(v0.y, 0.f);
                    v1.x = fmaxf(v1.x, 0.f); v1.y = fmaxf(v1.y, 0.f);
                }
                if (F32OUT) {
                    *(float2*)(Cf + (size_t)mlo * N + n) = v0;
                    *(float2*)(Cf + (size_t)(mlo + 8) * N + n) = v1;
                } else {
                    *(uint32_t*)(Ch + (size_t)mlo * N + n) = pack_f16x2(v0.x, v0.y);
                    *(uint32_t*)(Ch + (size_t)(mlo + 8) * N + n) = pack_f16x2(v1.x, v1.y);
                }
            }
        }
    }
}

// =====================================================================
// Flash attention, fp16 m16n8k16, ldmatrix, zero-copy P, f16x2 ex2,
// ones-MMA row sums. (round-14 proven, unchanged)
// =====================================================================
#define AO_Q  0
#define AO_K0 16384
#define AO_K1 24576
#define AO_V0 32768
#define AO_V1 40960
#define ATTN_SMEM_BYTES 49152
#define H2_ONES 0x3C003C00u

__global__ void __launch_bounds__(256, 2) attn_mma(
    const __half* __restrict__ Qs, const __half* __restrict__ Kn,
    const __half* __restrict__ Vt, __half* __restrict__ O)
{
    extern __shared__ char smc[];
    const uint32_t sb = smem_u32(smc);

    const int tid = threadIdx.x;
    const int wid = tid >> 5, l = tid & 31;
    const int lr = l >> 2, la = l & 3;
    const int q0 = blockIdx.x * 128;
    const int h  = blockIdx.y, b = blockIdx.z;

    const __half* Qg = Qs + ((size_t)b * SEQ + q0) * DM + h * 64;
    const __half* Kg = Kn + (size_t)b * SEQ * DM + h * 64;
    const __half* Vg = Vt + ((size_t)b * NH + h) * 64 * SEQ;

    const uint32_t ar7  = (uint32_t)(l & 7);
    const uint32_t achi = (uint32_t)(l >> 4);
    const uint32_t bchi = (uint32_t)((l >> 3) & 1);
    const uint32_t bjh  = (uint32_t)((l >> 4) & 1);
    const uint32_t qrel = (uint32_t)((wid * 16 + (l & 15)) * 128);
    uint32_t krel[4];
#pragma unroll
    for (int p = 0; p < 4; p++)
        krel[p] = (uint32_t)(((p * 2 + bjh) * 8 + (l & 7)) * 128);

    const int qrow = tid >> 1, qcb = (tid & 1) * 4;
    const int krow = tid >> 2, kcb = (tid & 3) * 2;

    {
#pragma unroll
        for (int i = 0; i < 4; i++) {
            int c = qcb + i;
            CP_ASYNC16(sb + AO_Q + (uint32_t)(qrow * 128 + ((c ^ (qrow & 7)) * 16)),
                       Qg + (size_t)qrow * DM + c * 8);
        }
#pragma unroll
        for (int i = 0; i < 2; i++) {
            int c = kcb + i;
            uint32_t sw = (uint32_t)(krow * 128 + ((c ^ (krow & 7)) * 16));
            CP_ASYNC16(sb + AO_K0 + sw, Kg + (size_t)krow * DM + c * 8);
            CP_ASYNC16(sb + AO_V0 + sw, Vg + (size_t)krow * SEQ + c * 8);
        }
        CP_COMMIT();
    }
    CP_WAIT0();
    __syncthreads();

    uint32_t aq[4][4];
#pragma unroll
    for (int kc = 0; kc < 4; kc++) {
        uint32_t axo = ((2u * kc + achi) ^ ar7) * 16u;
        LDSM_X4(aq[kc][0], aq[kc][1], aq[kc][2], aq[kc][3], sb + AO_Q + qrel + axo);
    }

    float o[8][4] = {};
    float ls[4] = {0.f, 0.f, 0.f, 0.f};
    const int NT = SEQ / 64;

    for (int t = 0; t < NT; t++) {
        if (t + 1 < NT) {
            int j0 = (t + 1) * 64;
            uint32_t ok = ((t + 1) & 1) ? AO_K1 : AO_K0;
            uint32_t ov = ((t + 1) & 1) ? AO_V1 : AO_V0;
#pragma unroll
            for (int i = 0; i < 2; i++) {
                int c = kcb + i;
                uint32_t sw = (uint32_t)(krow * 128 + ((c ^ (krow & 7)) * 16));
                CP_ASYNC16(sb + ok + sw, Kg + (size_t)(j0 + krow) * DM + c * 8);
                CP_ASYNC16(sb + ov + sw, Vg + (size_t)krow * SEQ + j0 + c * 8);
            }
            CP_COMMIT();
        }

        const uint32_t Kb = sb + ((t & 1) ? AO_K1 : AO_K0);
        const uint32_t Vb = sb + ((t & 1) ? AO_V1 : AO_V0);

        float s[8][4] = {};
#pragma unroll
        for (int kc = 0; kc < 4; kc++) {
            const uint32_t bxo = ((2u * kc + bchi) ^ ar7) * 16u;
            uint32_t bk[8][2];
            LDSM_X4(bk[0][0], bk[0][1], bk[1][0], bk[1][1], Kb + krel[0] + bxo);
            LDSM_X4(bk[2][0], bk[2][1], bk[3][0], bk[3][1], Kb + krel[1] + bxo);
            LDSM_X4(bk[4][0], bk[4][1], bk[5][0], bk[5][1], Kb + krel[2] + bxo);
            LDSM_X4(bk[6][0], bk[6][1], bk[7][0], bk[7][1], Kb + krel[3] + bxo);
#pragma unroll
            for (int j = 0; j < 8; j++)
                MMA_F16(s[j][0], s[j][1], s[j][2], s[j][3],
                        aq[kc][0], aq[kc][1], aq[kc][2], aq[kc][3], bk[j][0], bk[j][1]);
        }

        uint32_t ap[4][4];
#pragma unroll
        for (int kg = 0; kg < 4; kg++) {
            ap[kg][0] = h2ex2(pack_f16x2(s[2*kg][0],   s[2*kg][1]));
            ap[kg][1] = h2ex2(pack_f16x2(s[2*kg][2],   s[2*kg][3]));
            ap[kg][2] = h2ex2(pack_f16x2(s[2*kg+1][0], s[2*kg+1][1]));
            ap[kg][3] = h2ex2(pack_f16x2(s[2*kg+1][2], s[2*kg+1][3]));
        }

#pragma unroll
        for (int kg = 0; kg < 4; kg++)
            MMA_F16(ls[0], ls[1], ls[2], ls[3],
                    ap[kg][0], ap[kg][1], ap[kg][2], ap[kg][3], H2_ONES, H2_ONES);

#pragma unroll
        for (int kg = 0; kg < 4; kg++) {
            const uint32_t bxo = ((2u * kg + bchi) ^ ar7) * 16u;
            uint32_t bv[8][2];
            LDSM_X4(bv[0][0], bv[0][1], bv[1][0], bv[1][1], Vb + krel[0] + bxo);
            LDSM_X4(bv[2][0], bv[2][1], bv[3][0], bv[3][1], Vb + krel[1] + bxo);
            LDSM_X4(bv[4][0], bv[4][1], bv[5][0], bv[5][1], Vb + krel[2] + bxo);
            LDSM_X4(bv[6][0], bv[6][1], bv[7][0], bv[7][1], Vb + krel[3] + bxo);
#pragma unroll
            for (int j = 0; j < 8; j++)
                MMA_F16(o[j][0], o[j][1], o[j][2], o[j][3],
                        ap[kg][0], ap[kg][1], ap[kg][2], ap[kg][3], bv[j][0], bv[j][1]);
        }

        if (t + 1 < NT) {
            CP_WAIT0();
            __syncthreads();
        }
    }

    float invl = 1.f / ls[0], invh = 1.f / ls[2];
    __half* d0 = O + ((size_t)b * SEQ + q0 + wid * 16 + lr) * DM + h * 64;
    __half* d8 = d0 + 8 * DM;
#pragma unroll
    for (int j = 0; j < 8; j++) {
        *(uint32_t*)(d0 + j*8 + 2*la) = pack_f16x2(o[j][0] * invl, o[j][1] * invl);
        *(uint32_t*)(d8 + j*8 + 2*la) = pack_f16x2(o[j][2] * invh, o[j][3] * invh);
    }
}

// =====================================================================
// LayerNorm: warp per row, 8 rows per 256-thread block.
// =====================================================================
template<bool HALF_OUT>
__global__ void __launch_bounds__(256) ln_kernel(
    const float* __restrict__ X, const float* __restrict__ g,
    const float* __restrict__ be, float* __restrict__ Yf, __half* __restrict__ Yh)
{
    const int row = blockIdx.x * 8 + (threadIdx.x >> 5);
    const int l = threadIdx.x & 31;
    const float* x = X + (size_t)row * DM + l * 4;

    float4 v[4];
    float s = 0.f, q = 0.f;
#pragma unroll
    for (int i = 0; i < 4; i++) {
        v[i] = *(const float4*)(x + i * 128);
        s += v[i].x + v[i].y + v[i].z + v[i].w;
        q += v[i].x * v[i].x + v[i].y * v[i].y + v[i].z * v[i].z + v[i].w * v[i].w;
    }
#pragma unroll
    for (int o = 16; o; o >>= 1) {
        s += __shfl_xor_sync(0xFFFFFFFFu, s, o);
        q += __shfl_xor_sync(0xFFFFFFFFu, q, o);
    }
    float mean = s * (1.f / DM);
    float var  = q * (1.f / DM) - mean * mean;
    float rstd = rsqrtf(var + 1e-5f);

#pragma unroll
    for (int i = 0; i < 4; i++) {
        float4 gv = *(const float4*)(g  + l * 4 + i * 128);
        float4 bv = *(const float4*)(be + l * 4 + i * 128);
        float4 r;
        r.x = (v[i].x - mean) * rstd * gv.x + bv.x;
        r.y = (v[i].y - mean) * rstd * gv.y + bv.y;
        r.z = (v[i].z - mean) * rstd * gv.z + bv.z;
        r.w = (v[i].w - mean) * rstd * gv.w + bv.w;
        if (HALF_OUT) {
            uint2 pk;
            pk.x = pack_f16x2(r.x, r.y);
            pk.y = pack_f16x2(r.z, r.w);
            *(uint2*)(Yh + (size_t)row * DM + l * 4 + i * 128) = pk;
        } else {
            *(float4*)(Yf + (size_t)row * DM + l * 4 + i * 128) = r;
        }
    }
}

// =====================================================================
extern "C" void kernel_launch(void* const* d_in, const int* in_sizes, int n_in,
                              void* d_out, int out_size)
{
    const float* z_in = (const float*)d_in[0];
    const float* Wq = (const float*)d_in[1];
    const float* bq = (const float*)d_in[2];
    const float* Wk = (const float*)d_in[3];
    const float* bk = (const float*)d_in[4];
    const float* Wv = (const float*)d_in[5];
    const float* bv = (const float*)d_in[6];
    const float* Wo = (const float*)d_in[7];
    const float* bo = (const float*)d_in[8];
    const float* W1 = (const float*)d_in[9];
    const float* b1 = (const float*)d_in[10];
    const float* W2 = (const float*)d_in[11];
    const float* b2 = (const float*)d_in[12];
    const float* g1 = (const float*)d_in[13];
    const float* be1 = (const float*)d_in[14];
    const float* g2 = (const float*)d_in[15];
    const float* be2 = (const float*)d_in[16];
    float* out = (float*)d_out;

    __half *Qsb, *Knb, *Vtb, *Ob, *Zb, *H1b;
    __half *WqkvTb, *WoTb, *W1Tb, *W2Tb;
    float *Tb, *bqkvb;
    cudaGetSymbolAddress((void**)&Qsb, g_Qs);
    cudaGetSymbolAddress((void**)&Knb, g_Kn);
    cudaGetSymbolAddress((void**)&Vtb, g_Vt);
    cudaGetSymbolAddress((void**)&Ob, g_O);
    cudaGetSymbolAddress((void**)&Tb, g_T);
    cudaGetSymbolAddress((void**)&Zb, g_Z);
    cudaGetSymbolAddress((void**)&H1b, g_H1);
    cudaGetSymbolAddress((void**)&WqkvTb, g_WqkvT);
    cudaGetSymbolAddress((void**)&WoTb, g_WoT);
    cudaGetSymbolAddress((void**)&W1Tb, g_W1T);
    cudaGetSymbolAddress((void**)&W2Tb, g_W2T);
    cudaGetSymbolAddress((void**)&bqkvb, g_bqkv);

    cudaFuncSetAttribute(attn_mma,
        cudaFuncAttributeMaxDynamicSharedMemorySize, ATTN_SMEM_BYTES);
    cudaFuncSetAttribute(mma_gemm<3, false, false, false, true>,
        cudaFuncAttributeMaxDynamicSharedMemorySize, G_SMEM(3));
    cudaFuncSetAttribute(mma_gemm<3, true, false, false, false>,
        cudaFuncAttributeMaxDynamicSharedMemorySize, G_SMEM(3));
    cudaFuncSetAttribute(mma_gemm<5, false, true, true, false>,
        cudaFuncAttributeMaxDynamicSharedMemorySize, G_SMEM(5));

    prep_weights<<<dim3(4096, 5), 256>>>(Wq, Wk, Wv, Wo, W1, W2, bq, bk, bv,
                                         WqkvTb, WoTb, W1Tb, W2Tb, bqkvb);
    round_z<<<(ROWS * DM) / 256, 256>>>(z_in, Zb);

    dim3 blk(256);
    dim3 gQKV(QKV_LD / 128, ROWS / 128);   // (12, 32) = 384
    dim3 gP  (DM  / 128, ROWS / 128);      // (4, 32)  = 128
    dim3 gF1 (DFF / 128, ROWS / 128);      // (16, 32) = 512
    dim3 gAttn(SEQ / 128, NH, BB);         // (16, 8, 2)

    for (int it = 0; it < 4; it++) {
        mma_gemm<3, false, false, false, true><<<gQKV, blk, G_SMEM(3)>>>(
            Zb, WqkvTb, bqkvb, nullptr, nullptr, Qsb, Knb, Vtb, ROWS, QKV_LD, DM);

        attn_mma<<<gAttn, blk, ATTN_SMEM_BYTES>>>(Qsb, Knb, Vtb, Ob);

        // Wo projection + residual: 5-stage deep pipeline (grid 128, 1 CTA/SM)
        mma_gemm<5, false, true, true, false><<<gP, blk, G_SMEM(5)>>>(
            Ob, WoTb, bo, Zb, Tb, nullptr, nullptr, nullptr, ROWS, DM, DM);

        if (it == 3) {
            ln_kernel<false><<<ROWS / 8, 256>>>(Tb, g1, be1, out, nullptr);
        } else {
            ln_kernel<true><<<ROWS / 8, 256>>>(Tb, g1, be1, nullptr, Zb);
            mma_gemm<3, true, false, false, false><<<gF1, blk, G_SMEM(3)>>>(
                Zb, W1Tb, b1, nullptr, nullptr, H1b, nullptr, nullptr, ROWS, DFF, DM);
            mma_gemm<5, false, true, true, false><<<gP, blk, G_SMEM(5)>>>(
                H1b, W2Tb, b2, Zb, Tb, nullptr, nullptr, nullptr, ROWS, DM, DFF);
            ln_kernel<true><<<ROWS / 8, 256>>>(Tb, g2, be2, nullptr, Zb);
        }
    }
}

// round 16
// speedup vs baseline: 1.0202x; 1.0202x over previous
#include <cuda_runtime.h>
#include <cuda_fp16.h>
#include <cstdint>
#include <math.h>

#define DM   512
#define DFF  2048
#define NH   8
#define DH   64
#define BB   2
#define SEQ  2048
#define ROWS (BB*SEQ)   // 4096
#define QKV_LD 1536

// Q projection pre-scale: (1/sqrt(64)) * log2(e), so softmax uses ex2 directly
#define QSCALE 0.18033688011112042f

// ---------------- static scratch (no allocations allowed) ----------------
__device__ __half  g_Qs  [ROWS*DM];           // Q, pre-scaled
__device__ __half  g_Kn  [ROWS*DM];           // K, natural layout
__device__ __half  g_Vt  [BB*NH*DH*SEQ];      // V transposed [b,h,dim][key]
__device__ __half  g_O   [ROWS*DM];
__device__ float   g_T   [ROWS*DM];           // fp32 (LN input)
__device__ __half  g_Z   [ROWS*DM];
__device__ __half  g_H1  [ROWS*DFF];
__device__ __half  g_WqkvT[QKV_LD*DM];        // [n][k]; Wq part pre-scaled
__device__ __half  g_WoT [DM*DM];
__device__ __half  g_W1T [DFF*DM];
__device__ __half  g_W2T [DM*DFF];
__device__ float   g_bqkv[QKV_LD];

__device__ __forceinline__ uint32_t pack_f16x2(float lo, float hi) {
    uint32_t r;
    asm("cvt.rn.f16x2.f32 %0, %1, %2;" : "=r"(r) : "f"(hi), "f"(lo));
    return r;
}
__device__ __forceinline__ uint32_t h2ex2(uint32_t x) {
    uint32_t r;
    asm("ex2.approx.f16x2 %0, %1;" : "=r"(r) : "r"(x));
    return r;
}
__device__ __forceinline__ uint32_t smem_u32(const void* p) {
    uint32_t a;
    asm("{ .reg .u64 t; cvta.to.shared.u64 t, %1; cvt.u32.u64 %0, t; }" : "=r"(a) : "l"(p));
    return a;
}

#define MMA_F16(d0,d1,d2,d3, a0,a1,a2,a3, b0,b1) \
    asm volatile("mma.sync.aligned.m16n8k16.row.col.f32.f16.f16.f32 " \
        "{%0,%1,%2,%3}, {%4,%5,%6,%7}, {%8,%9}, {%0,%1,%2,%3};" \
        : "+f"(d0), "+f"(d1), "+f"(d2), "+f"(d3) \
        : "r"(a0), "r"(a1), "r"(a2), "r"(a3), "r"(b0), "r"(b1))

#define LDSM_X4(r0,r1,r2,r3, addr) \
    asm volatile("ldmatrix.sync.aligned.m8n8.x4.shared.b16 {%0,%1,%2,%3}, [%4];" \
        : "=r"(r0), "=r"(r1), "=r"(r2), "=r"(r3) : "r"(addr))

#define CP_ASYNC16(saddr, gptr) \
    asm volatile("cp.async.cg.shared.global [%0], [%1], 16;" :: "r"(saddr), "l"(gptr))
#define CP_COMMIT() asm volatile("cp.async.commit_group;" ::: "memory")
#define CP_WAIT1()  asm volatile("cp.async.wait_group 1;" ::: "memory")
#define CP_WAIT0()  asm volatile("cp.async.wait_group 0;" ::: "memory")

// =====================================================================
// prep_weights: transposes + fp16 conversion + bias concat + z rounding.
// One launch covers all preprocessing (blockIdx.y selects target).
// =====================================================================
__global__ void prep_weights(
    const float* __restrict__ Wq, const float* __restrict__ Wk,
    const float* __restrict__ Wv, const float* __restrict__ Wo,
    const float* __restrict__ W1, const float* __restrict__ W2,
    const float* __restrict__ bq, const float* __restrict__ bk,
    const float* __restrict__ bv, const float* __restrict__ z_in,
    __half* __restrict__ QKVT, __half* __restrict__ WoT,
    __half* __restrict__ W1T,  __half* __restrict__ W2T,
    float* __restrict__ bqkv,  __half* __restrict__ Z)
{
    int idx = blockIdx.x * 256 + threadIdx.x;
    switch (blockIdx.y) {
    case 0: {
        if (idx >= QKV_LD * DM) return;
        int n = idx >> 9, k = idx & 511;
        const float* W = (n < 512) ? Wq : ((n < 1024) ? Wk : Wv);
        float sc = (n < 512) ? QSCALE : 1.0f;
        int nl = n & 511;
        QKVT[idx] = __float2half(sc * W[((size_t)(nl >> 6) * 512 + k) * 64 + (nl & 63)]);
    } break;
    case 1: {
        if (idx >= DM * DM) return;
        int n = idx >> 9, k = idx & 511;
        WoT[idx] = __float2half(Wo[(size_t)k * DM + n]);
    } break;
    case 2: {
        if (idx >= DFF * DM) return;
        int n = idx >> 9, k = idx & 511;
        W1T[idx] = __float2half(W1[(size_t)k * DFF + n]);
    } break;
    case 3: {
        if (idx >= DM * DFF) return;
        int n = idx >> 11, k = idx & 2047;
        W2T[idx] = __float2half(W2[(size_t)k * DM + n]);
    } break;
    case 4: {
        if (idx >= 512) return;
        bqkv[idx]        = bq[idx] * QSCALE;
        bqkv[512 + idx]  = bk[idx];
        bqkv[1024 + idx] = bv[idx];
    } break;
    case 5: {
        int i = idx * 2;
        if (i >= ROWS * DM) return;
        float2 v = *(const float2*)(z_in + i);
        *(uint32_t*)(Z + i) = pack_f16x2(v.x, v.y);
    } break;
    }
}

// =====================================================================
// FP16 mma.sync GEMM (m16n8k16), cp.async 3-stage, ldmatrix fragments.
// CTA 128x128, K-slab 64 (128B rows, chunk-XOR swizzle), 2 CTA/SM.
// (round-12/14 proven config, used for ALL dense GEMMs)
// =====================================================================
#define G_SMEM_BYTES (3 * 32768)   // 98304

template<bool RELU, bool RES, bool F32OUT, bool QKVO>
__global__ void __launch_bounds__(256, 2) mma_gemm(
    const __half* __restrict__ A, const __half* __restrict__ BT,
    const float* __restrict__ bias, const __half* __restrict__ R,
    float* __restrict__ Cf, __half* __restrict__ Ch,
    __half* __restrict__ CK, __half* __restrict__ CV,
    int M, int N, int K)
{
    extern __shared__ char smc[];
    const uint32_t sbase = smem_u32(smc);

    const int tid = threadIdx.x;
    const int wid = tid >> 5, l = tid & 31;
    const int lr  = l >> 2, la = l & 3;
    const int wm  = wid & 1;
    const int wn  = wid >> 1;
    const int m0  = blockIdx.y * 128;
    const int n0  = blockIdx.x * 128;
    const int NS  = K >> 6;

    const uint32_t ar7   = (uint32_t)(l & 7);
    const uint32_t achi  = (uint32_t)(l >> 4);
    const uint32_t bchi  = (uint32_t)((l >> 3) & 1);
    const uint32_t bjh   = (uint32_t)((l >> 4) & 1);
    uint32_t arel[4];
#pragma unroll
    for (int i = 0; i < 4; i++)
        arel[i] = (uint32_t)((wm * 64 + i * 16 + (l & 15)) * 128);
    uint32_t brel[2];
#pragma unroll
    for (int p = 0; p < 2; p++)
        brel[p] = (uint32_t)((wn * 32 + (p * 2 + bjh) * 8 + (l & 7)) * 128);

    const int srow = tid >> 1;
    const int cb   = (tid & 1) * 4;
    uint32_t soff[4];
#pragma unroll
    for (int i = 0; i < 4; i++)
        soff[i] = (uint32_t)(srow * 128) + (uint32_t)(((cb + i) ^ (srow & 7)) * 16);

    const __half* Ag = A  + (size_t)m0 * K;
    const __half* Bg = BT + (size_t)n0 * K;

#pragma unroll
    for (int s = 0; s < 2; s++) {
        uint32_t st = sbase + (uint32_t)s * 32768u;
        const __half* Ap = Ag + (size_t)srow * K + s * 64 + cb * 8;
        const __half* Bp = Bg + (size_t)srow * K + s * 64 + cb * 8;
#pragma unroll
        for (int i = 0; i < 4; i++) {
            CP_ASYNC16(st + soff[i],           Ap + i * 8);
            CP_ASYNC16(st + 16384u + soff[i],  Bp + i * 8);
        }
        CP_COMMIT();
    }

    float acc[4][4][4] = {};

    for (int s = 0; s < NS; s++) {
        CP_WAIT1();
        __syncthreads();

        if (s + 2 < NS) {
            int sn = s + 2;
            uint32_t st = sbase + (uint32_t)(sn % 3) * 32768u;
            const __half* Ap = Ag + (size_t)srow * K + sn * 64 + cb * 8;
            const __half* Bp = Bg + (size_t)srow * K + sn * 64 + cb * 8;
#pragma unroll
            for (int i = 0; i < 4; i++) {
                CP_ASYNC16(st + soff[i],          Ap + i * 8);
                CP_ASYNC16(st + 16384u + soff[i], Bp + i * 8);
            }
            CP_COMMIT();
        }

        const uint32_t stA = sbase + (uint32_t)(s % 3) * 32768u;
        const uint32_t stB = stA + 16384u;

#pragma unroll
        for (int kc = 0; kc < 4; kc++) {
            const uint32_t axo = ((2u * kc + achi) ^ ar7) * 16u;
            const uint32_t bxo = ((2u * kc + bchi) ^ ar7) * 16u;
            uint32_t a[4][4], b[4][2];
#pragma unroll
            for (int i = 0; i < 4; i++)
                LDSM_X4(a[i][0], a[i][1], a[i][2], a[i][3], stA + arel[i] + axo);
            LDSM_X4(b[0][0], b[0][1], b[1][0], b[1][1], stB + brel[0] + bxo);
            LDSM_X4(b[2][0], b[2][1], b[3][0], b[3][1], stB + brel[1] + bxo);
#pragma unroll
            for (int i = 0; i < 4; i++)
#pragma unroll
                for (int j = 0; j < 4; j++)
                    MMA_F16(acc[i][j][0], acc[i][j][1], acc[i][j][2], acc[i][j][3],
                            a[i][0], a[i][1], a[i][2], a[i][3], b[j][0], b[j][1]);
        }
    }

    // ---- epilogue ----
#pragma unroll
    for (int i = 0; i < 4; i++) {
        int mlo = m0 + wm * 64 + i * 16 + lr;
#pragma unroll
        for (int j = 0; j < 4; j++) {
            int n = n0 + wn * 32 + j * 8 + la * 2;
            float2 bz = *(const float2*)(bias + n);
            float2 v0 = make_float2(acc[i][j][0] + bz.x, acc[i][j][1] + bz.y);
            float2 v1 = make_float2(acc[i][j][2] + bz.x, acc[i][j][3] + bz.y);
            if (QKVO) {
                int part = n >> 9, nl = n & 511;
                if (part == 0) {
                    *(uint32_t*)(Ch + (size_t)mlo * DM + nl) = pack_f16x2(v0.x, v0.y);
                    *(uint32_t*)(Ch + (size_t)(mlo + 8) * DM + nl) = pack_f16x2(v1.x, v1.y);
                } else if (part == 1) {
                    *(uint32_t*)(CK + (size_t)mlo * DM + nl) = pack_f16x2(v0.x, v0.y);
                    *(uint32_t*)(CK + (size_t)(mlo + 8) * DM + nl) = pack_f16x2(v1.x, v1.y);
                } else {
                    int h = nl >> 6, d = nl & 63;
                    int key = mlo & (SEQ - 1);
                    int bb_ = mlo >> 11;
                    size_t vrow = ((size_t)bb_ * NH + h) * 64 + d;
                    CV[vrow * SEQ + key]           = __float2half(v0.x);
                    CV[(vrow + 1) * SEQ + key]     = __float2half(v0.y);
                    CV[vrow * SEQ + key + 8]       = __float2half(v1.x);
                    CV[(vrow + 1) * SEQ + key + 8] = __float2half(v1.y);
                }
            } else {
                if (RES) {
                    float2 r0 = __half22float2(*(const __half2*)(R + (size_t)mlo * N + n));
                    float2 r1 = __half22float2(*(const __half2*)(R + (size_t)(mlo + 8) * N + n));
                    v0.x += r0.x; v0.y += r0.y; v1.x += r1.x; v1.y += r1.y;
                }
                if (RELU) {
                    v0.x = fmaxf(v0.x, 0.f); v0.y = fmaxf(v0.y, 0.f);
                    v1.x = fmaxf(v1.x, 0.f); v1.y = fmaxf(v1.y, 0.f);
                }
                if (F32OUT) {
                    *(float2*)(Cf + (size_t)mlo * N + n) = v0;
                    *(float2*)(Cf + (size_t)(mlo + 8) * N + n) = v1;
                } else {
                    *(uint32_t*)(Ch + (size_t)mlo * N + n) = pack_f16x2(v0.x, v0.y);
                    *(uint32_t*)(Ch + (size_t)(mlo + 8) * N + n) = pack_f16x2(v1.x, v1.y);
                }
            }
        }
    }
}

// =====================================================================
// Flash attention, fp16 m16n8k16, ldmatrix, zero-copy P, f16x2 ex2,
// ones-MMA row sums. (round-14 proven, unchanged)
// =====================================================================
#define AO_Q  0
#define AO_K0 16384
#define AO_K1 24576
#define AO_V0 32768
#define AO_V1 40960
#define ATTN_SMEM_BYTES 49152
#define H2_ONES 0x3C003C00u

__global__ void __launch_bounds__(256, 2) attn_mma(
    const __half* __restrict__ Qs, const __half* __restrict__ Kn,
    const __half* __restrict__ Vt, __half* __restrict__ O)
{
    extern __shared__ char smc[];
    const uint32_t sb = smem_u32(smc);

    const int tid = threadIdx.x;
    const int wid = tid >> 5, l = tid & 31;
    const int lr = l >> 2, la = l & 3;
    const int q0 = blockIdx.x * 128;
    const int h  = blockIdx.y, b = blockIdx.z;

    const __half* Qg = Qs + ((size_t)b * SEQ + q0) * DM + h * 64;
    const __half* Kg = Kn + (size_t)b * SEQ * DM + h * 64;
    const __half* Vg = Vt + ((size_t)b * NH + h) * 64 * SEQ;

    const uint32_t ar7  = (uint32_t)(l & 7);
    const uint32_t achi = (uint32_t)(l >> 4);
    const uint32_t bchi = (uint32_t)((l >> 3) & 1);
    const uint32_t bjh  = (uint32_t)((l >> 4) & 1);
    const uint32_t qrel = (uint32_t)((wid * 16 + (l & 15)) * 128);
    uint32_t krel[4];
#pragma unroll
    for (int p = 0; p < 4; p++)
        krel[p] = (uint32_t)(((p * 2 + bjh) * 8 + (l & 7)) * 128);

    const int qrow = tid >> 1, qcb = (tid & 1) * 4;
    const int krow = tid >> 2, kcb = (tid & 3) * 2;

    {
#pragma unroll
        for (int i = 0; i < 4; i++) {
            int c = qcb + i;
            CP_ASYNC16(sb + AO_Q + (uint32_t)(qrow * 128 + ((c ^ (qrow & 7)) * 16)),
                       Qg + (size_t)qrow * DM + c * 8);
        }
#pragma unroll
        for (int i = 0; i < 2; i++) {
            int c = kcb + i;
            uint32_t sw = (uint32_t)(krow * 128 + ((c ^ (krow & 7)) * 16));
            CP_ASYNC16(sb + AO_K0 + sw, Kg + (size_t)krow * DM + c * 8);
            CP_ASYNC16(sb + AO_V0 + sw, Vg + (size_t)krow * SEQ + c * 8);
        }
        CP_COMMIT();
    }
    CP_WAIT0();
    __syncthreads();

    uint32_t aq[4][4];
#pragma unroll
    for (int kc = 0; kc < 4; kc++) {
        uint32_t axo = ((2u * kc + achi) ^ ar7) * 16u;
        LDSM_X4(aq[kc][0], aq[kc][1], aq[kc][2], aq[kc][3], sb + AO_Q + qrel + axo);
    }

    float o[8][4] = {};
    float ls[4] = {0.f, 0.f, 0.f, 0.f};
    const int NT = SEQ / 64;

    for (int t = 0; t < NT; t++) {
        if (t + 1 < NT) {
            int j0 = (t + 1) * 64;
            uint32_t ok = ((t + 1) & 1) ? AO_K1 : AO_K0;
            uint32_t ov = ((t + 1) & 1) ? AO_V1 : AO_V0;
#pragma unroll
            for (int i = 0; i < 2; i++) {
                int c = kcb + i;
                uint32_t sw = (uint32_t)(krow * 128 + ((c ^ (krow & 7)) * 16));
                CP_ASYNC16(sb + ok + sw, Kg + (size_t)(j0 + krow) * DM + c * 8);
                CP_ASYNC16(sb + ov + sw, Vg + (size_t)krow * SEQ + j0 + c * 8);
            }
            CP_COMMIT();
        }

        const uint32_t Kb = sb + ((t & 1) ? AO_K1 : AO_K0);
        const uint32_t Vb = sb + ((t & 1) ? AO_V1 : AO_V0);

        float s[8][4] = {};
#pragma unroll
        for (int kc = 0; kc < 4; kc++) {
            const uint32_t bxo = ((2u * kc + bchi) ^ ar7) * 16u;
            uint32_t bk[8][2];
            LDSM_X4(bk[0][0], bk[0][1], bk[1][0], bk[1][1], Kb + krel[0] + bxo);
            LDSM_X4(bk[2][0], bk[2][1], bk[3][0], bk[3][1], Kb + krel[1] + bxo);
            LDSM_X4(bk[4][0], bk[4][1], bk[5][0], bk[5][1], Kb + krel[2] + bxo);
            LDSM_X4(bk[6][0], bk[6][1], bk[7][0], bk[7][1], Kb + krel[3] + bxo);
#pragma unroll
            for (int j = 0; j < 8; j++)
                MMA_F16(s[j][0], s[j][1], s[j][2], s[j][3],
                        aq[kc][0], aq[kc][1], aq[kc][2], aq[kc][3], bk[j][0], bk[j][1]);
        }

        uint32_t ap[4][4];
#pragma unroll
        for (int kg = 0; kg < 4; kg++) {
            ap[kg][0] = h2ex2(pack_f16x2(s[2*kg][0],   s[2*kg][1]));
            ap[kg][1] = h2ex2(pack_f16x2(s[2*kg][2],   s[2*kg][3]));
            ap[kg][2] = h2ex2(pack_f16x2(s[2*kg+1][0], s[2*kg+1][1]));
            ap[kg][3] = h2ex2(pack_f16x2(s[2*kg+1][2], s[2*kg+1][3]));
        }

#pragma unroll
        for (int kg = 0; kg < 4; kg++)
            MMA_F16(ls[0], ls[1], ls[2], ls[3],
                    ap[kg][0], ap[kg][1], ap[kg][2], ap[kg][3], H2_ONES, H2_ONES);

#pragma unroll
        for (int kg = 0; kg < 4; kg++) {
            const uint32_t bxo = ((2u * kg + bchi) ^ ar7) * 16u;
            uint32_t bv[8][2];
            LDSM_X4(bv[0][0], bv[0][1], bv[1][0], bv[1][1], Vb + krel[0] + bxo);
            LDSM_X4(bv[2][0], bv[2][1], bv[3][0], bv[3][1], Vb + krel[1] + bxo);
            LDSM_X4(bv[4][0], bv[4][1], bv[5][0], bv[5][1], Vb + krel[2] + bxo);
            LDSM_X4(bv[6][0], bv[6][1], bv[7][0], bv[7][1], Vb + krel[3] + bxo);
#pragma unroll
            for (int j = 0; j < 8; j++)
                MMA_F16(o[j][0], o[j][1], o[j][2], o[j][3],
                        ap[kg][0], ap[kg][1], ap[kg][2], ap[kg][3], bv[j][0], bv[j][1]);
        }

        if (t + 1 < NT) {
            CP_WAIT0();
            __syncthreads();
        }
    }

    float invl = 1.f / ls[0], invh = 1.f / ls[2];
    __half* d0 = O + ((size_t)b * SEQ + q0 + wid * 16 + lr) * DM + h * 64;
    __half* d8 = d0 + 8 * DM;
#pragma unroll
    for (int j = 0; j < 8; j++) {
        *(uint32_t*)(d0 + j*8 + 2*la) = pack_f16x2(o[j][0] * invl, o[j][1] * invl);
        *(uint32_t*)(d8 + j*8 + 2*la) = pack_f16x2(o[j][2] * invh, o[j][3] * invh);
    }
}

// =====================================================================
// LayerNorm: warp per row, 8 rows per 256-thread block.
// =====================================================================
template<bool HALF_OUT>
__global__ void __launch_bounds__(256) ln_kernel(
    const float* __restrict__ X, const float* __restrict__ g,
    const float* __restrict__ be, float* __restrict__ Yf, __half* __restrict__ Yh)
{
    const int row = blockIdx.x * 8 + (threadIdx.x >> 5);
    const int l = threadIdx.x & 31;
    const float* x = X + (size_t)row * DM + l * 4;

    float4 v[4];
    float s = 0.f, q = 0.f;
#pragma unroll
    for (int i = 0; i < 4; i++) {
        v[i] = *(const float4*)(x + i * 128);
        s += v[i].x + v[i].y + v[i].z + v[i].w;
        q += v[i].x * v[i].x + v[i].y * v[i].y + v[i].z * v[i].z + v[i].w * v[i].w;
    }
#pragma unroll
    for (int o = 16; o; o >>= 1) {
        s += __shfl_xor_sync(0xFFFFFFFFu, s, o);
        q += __shfl_xor_sync(0xFFFFFFFFu, q, o);
    }
    float mean = s * (1.f / DM);
    float var  = q * (1.f / DM) - mean * mean;
    float rstd = rsqrtf(var + 1e-5f);

#pragma unroll
    for (int i = 0; i < 4; i++) {
        float4 gv = *(const float4*)(g  + l * 4 + i * 128);
        float4 bv = *(const float4*)(be + l * 4 + i * 128);
        float4 r;
        r.x = (v[i].x - mean) * rstd * gv.x + bv.x;
        r.y = (v[i].y - mean) * rstd * gv.y + bv.y;
        r.z = (v[i].z - mean) * rstd * gv.z + bv.z;
        r.w = (v[i].w - mean) * rstd * gv.w + bv.w;
        if (HALF_OUT) {
            uint2 pk;
            pk.x = pack_f16x2(r.x, r.y);
            pk.y = pack_f16x2(r.z, r.w);
            *(uint2*)(Yh + (size_t)row * DM + l * 4 + i * 128) = pk;
        } else {
            *(float4*)(Yf + (size_t)row * DM + l * 4 + i * 128) = r;
        }
    }
}

// =====================================================================
extern "C" void kernel_launch(void* const* d_in, const int* in_sizes, int n_in,
                              void* d_out, int out_size)
{
    const float* z_in = (const float*)d_in[0];
    const float* Wq = (const float*)d_in[1];
    const float* bq = (const float*)d_in[2];
    const float* Wk = (const float*)d_in[3];
    const float* bk = (const float*)d_in[4];
    const float* Wv = (const float*)d_in[5];
    const float* bv = (const float*)d_in[6];
    const float* Wo = (const float*)d_in[7];
    const float* bo = (const float*)d_in[8];
    const float* W1 = (const float*)d_in[9];
    const float* b1 = (const float*)d_in[10];
    const float* W2 = (const float*)d_in[11];
    const float* b2 = (const float*)d_in[12];
    const float* g1 = (const float*)d_in[13];
    const float* be1 = (const float*)d_in[14];
    const float* g2 = (const float*)d_in[15];
    const float* be2 = (const float*)d_in[16];
    float* out = (float*)d_out;

    __half *Qsb, *Knb, *Vtb, *Ob, *Zb, *H1b;
    __half *WqkvTb, *WoTb, *W1Tb, *W2Tb;
    float *Tb, *bqkvb;
    cudaGetSymbolAddress((void**)&Qsb, g_Qs);
    cudaGetSymbolAddress((void**)&Knb, g_Kn);
    cudaGetSymbolAddress((void**)&Vtb, g_Vt);
    cudaGetSymbolAddress((void**)&Ob, g_O);
    cudaGetSymbolAddress((void**)&Tb, g_T);
    cudaGetSymbolAddress((void**)&Zb, g_Z);
    cudaGetSymbolAddress((void**)&H1b, g_H1);
    cudaGetSymbolAddress((void**)&WqkvTb, g_WqkvT);
    cudaGetSymbolAddress((void**)&WoTb, g_WoT);
    cudaGetSymbolAddress((void**)&W1Tb, g_W1T);
    cudaGetSymbolAddress((void**)&W2Tb, g_W2T);
    cudaGetSymbolAddress((void**)&bqkvb, g_bqkv);

    cudaFuncSetAttribute(attn_mma,
        cudaFuncAttributeMaxDynamicSharedMemorySize, ATTN_SMEM_BYTES);
    cudaFuncSetAttribute(mma_gemm<false, false, false, true>,
        cudaFuncAttributeMaxDynamicSharedMemorySize, G_SMEM_BYTES);
    cudaFuncSetAttribute(mma_gemm<false, true, true, false>,
        cudaFuncAttributeMaxDynamicSharedMemorySize, G_SMEM_BYTES);
    cudaFuncSetAttribute(mma_gemm<true, false, false, false>,
        cudaFuncAttributeMaxDynamicSharedMemorySize, G_SMEM_BYTES);

    // one prep launch: transposes + fp16 conversion + bias concat + z rounding
    prep_weights<<<dim3(4096, 6), 256>>>(Wq, Wk, Wv, Wo, W1, W2, bq, bk, bv, z_in,
                                         WqkvTb, WoTb, W1Tb, W2Tb, bqkvb, Zb);

    dim3 blk(256);
    dim3 gQKV(QKV_LD / 128, ROWS / 128);   // (12, 32)
    dim3 gP  (DM  / 128, ROWS / 128);      // (4, 32)
    dim3 gF1 (DFF / 128, ROWS / 128);      // (16, 32)
    dim3 gAttn(SEQ / 128, NH, BB);         // (16, 8, 2)

    for (int it = 0; it < 4; it++) {
        mma_gemm<false, false, false, true><<<gQKV, blk, G_SMEM_BYTES>>>(
            Zb, WqkvTb, bqkvb, nullptr, nullptr, Qsb, Knb, Vtb, ROWS, QKV_LD, DM);

        attn_mma<<<gAttn, blk, ATTN_SMEM_BYTES>>>(Qsb, Knb, Vtb, Ob);

        mma_gemm<false, true, true, false><<<gP, blk, G_SMEM_BYTES>>>(
            Ob, WoTb, bo, Zb, Tb, nullptr, nullptr, nullptr, ROWS, DM, DM);

        if (it == 3) {
            ln_kernel<false><<<ROWS / 8, 256>>>(Tb, g1, be1, out, nullptr);
        } else {
            ln_kernel<true><<<ROWS / 8, 256>>>(Tb, g1, be1, nullptr, Zb);
            mma_gemm<true, false, false, false><<<gF1, blk, G_SMEM_BYTES>>>(
                Zb, W1Tb, b1, nullptr, nullptr, H1b, nullptr, nullptr, ROWS, DFF, DM);
            mma_gemm<false, true, true, false><<<gP, blk, G_SMEM_BYTES>>>(
                H1b, W2Tb, b2, Zb, Tb, nullptr, nullptr, nullptr, ROWS, DM, DFF);
            ln_kernel<true><<<ROWS / 8, 256>>>(Tb, g2, be2, nullptr, Zb);
        }
    }
}